// round 14
// baseline (speedup 1.0000x reference)
#include <cuda_runtime.h>

typedef unsigned int u32;

// CostVolume via banded tf32 GEMM (mma.sync m16n8k8), single-phase smem,
// LDS.128 k-window fragment loads, masked scalar-store epilogue.
// Block = (bh, 128-w tile), 256 threads / 8 warps.
// Warp (g = wid>>1, h = wid&1): G[32, 48] = L[rows 32g..+31, 0..63] .
//   R[rows 32g+48h .. +47, 0..63]^T    (R row r <-> src = w0-64+r)
// out[w,d] = G_band / 64, masked where src = w-1-d < 0.

namespace {
constexpr int Wd = 512, Cd = 64, Dd = 64, WT = 128;
constexpr int P        = 80;              // pitch (words): P/4 == 4 (mod 16)
constexpr int LS_WORDS = 128 * P;         // 10240
constexpr int SMEM_BYTES = (128 + 192) * P * 4;   // 102,400
}

__device__ __forceinline__ u32 f2tf32(float x) {
    u32 r;
    asm("cvt.rna.tf32.f32 %0, %1;" : "=r"(r) : "f"(x));
    return r;
}
__device__ __forceinline__ void mma_tf32(float* d, const u32* a, u32 b0, u32 b1) {
    asm("mma.sync.aligned.m16n8k8.row.col.f32.tf32.tf32.f32 "
        "{%0,%1,%2,%3}, {%4,%5,%6,%7}, {%8,%9}, {%0,%1,%2,%3};"
        : "+f"(d[0]), "+f"(d[1]), "+f"(d[2]), "+f"(d[3])
        : "r"(a[0]), "r"(a[1]), "r"(a[2]), "r"(a[3]), "r"(b0), "r"(b1));
}

__global__ __launch_bounds__(256, 2)
void cost_volume_mma_kernel(const float* __restrict__ left,
                            const float* __restrict__ right,
                            float* __restrict__ out) {
    extern __shared__ u32 sm[];
    u32* Ls = sm;                 // [w_local 0..127][c 0..63], pitch P
    u32* Rs = sm + LS_WORDS;      // [s_local 0..191][c 0..63], pitch P

    const int tid  = threadIdx.x;
    const int wid  = tid >> 5;        // 0..7
    const int lane = tid & 31;
    const int g    = wid >> 1;        // row group 0..3 (32 rows each)
    const int h    = wid & 1;         // col half 0..1 (48 cols each)
    const int q    = lane >> 2;       // 0..7
    const int c    = lane & 3;        // 0..3
    const int w0   = blockIdx.x * WT;
    const int bh   = blockIdx.y;

    const float* lrow = left  + (size_t)bh * Wd * Cd;
    const float* rrow = right + (size_t)bh * Wd * Cd;

    // ---- single fill: all 64 channels, tf32-converted at fill ----
#pragma unroll
    for (int i = 0; i < 8; i++) {
        const int idx = tid + 256 * i;          // 0..2047
        const int row = idx >> 4, c4 = idx & 15;
        const float4 v = *(const float4*)(lrow + (size_t)(w0 + row) * Cd + 4 * c4);
        uint4 t = make_uint4(f2tf32(v.x), f2tf32(v.y), f2tf32(v.z), f2tf32(v.w));
        *(uint4*)&Ls[row * P + 4 * c4] = t;
    }
#pragma unroll
    for (int i = 0; i < 12; i++) {
        const int idx = tid + 256 * i;          // 0..3071
        const int row = idx >> 4, c4 = idx & 15;
        const int s = max(w0 - 64 + row, 0);    // clamped; masked later
        const float4 v = *(const float4*)(rrow + (size_t)s * Cd + 4 * c4);
        uint4 t = make_uint4(f2tf32(v.x), f2tf32(v.y), f2tf32(v.z), f2tf32(v.w));
        *(uint4*)&Rs[row * P + 4 * c4] = t;
    }
    __syncthreads();

    // ---- compute: 4 supersteps of 16 k (k-window permuted, v4 loads) ----
    float acc[2][6][4];
#pragma unroll
    for (int mt = 0; mt < 2; mt++)
#pragma unroll
        for (int nt = 0; nt < 6; nt++)
#pragma unroll
            for (int r = 0; r < 4; r++) acc[mt][nt][r] = 0.0f;

    const u32* la_base = &Ls[(32 * g + q) * P];
    const u32* rb_base = &Rs[(32 * g + 48 * h + q) * P];
#pragma unroll
    for (int ki = 0; ki < 4; ki++) {
        const int kb = 16 * ki + 4 * c;
        uint4 alo[2], ahi[2], bv[6];
#pragma unroll
        for (int mt = 0; mt < 2; mt++) {
            alo[mt] = *(const uint4*)(la_base + (16 * mt) * P + kb);
            ahi[mt] = *(const uint4*)(la_base + (16 * mt + 8) * P + kb);
        }
#pragma unroll
        for (int nt = 0; nt < 6; nt++)
            bv[nt] = *(const uint4*)(rb_base + (8 * nt) * P + kb);

        // sub-step 0: regs {x, z} -> phys k = {4c, 4c+2}
        {
            u32 a[2][4];
#pragma unroll
            for (int mt = 0; mt < 2; mt++) {
                a[mt][0] = alo[mt].x; a[mt][1] = ahi[mt].x;
                a[mt][2] = alo[mt].z; a[mt][3] = ahi[mt].z;
            }
#pragma unroll
            for (int nt = 0; nt < 6; nt++) {
                mma_tf32(acc[0][nt], a[0], bv[nt].x, bv[nt].z);
                mma_tf32(acc[1][nt], a[1], bv[nt].x, bv[nt].z);
            }
        }
        // sub-step 1: regs {y, w} -> phys k = {4c+1, 4c+3}
        {
            u32 a[2][4];
#pragma unroll
            for (int mt = 0; mt < 2; mt++) {
                a[mt][0] = alo[mt].y; a[mt][1] = ahi[mt].y;
                a[mt][2] = alo[mt].w; a[mt][3] = ahi[mt].w;
            }
#pragma unroll
            for (int nt = 0; nt < 6; nt++) {
                mma_tf32(acc[0][nt], a[0], bv[nt].y, bv[nt].w);
                mma_tf32(acc[1][nt], a[1], bv[nt].y, bv[nt].w);
            }
        }
    }

    // ---- epilogue: direct masked scalar stores (alignment-safe) ----
    const float scale = 1.0f / 64.0f;
#pragma unroll
    for (int mt = 0; mt < 2; mt++)
#pragma unroll
        for (int rh = 0; rh < 2; rh++) {
            const int w_l = 32 * g + 16 * mt + 8 * rh + q;
            const int wg  = w0 + w_l;
            float* orow = out + ((size_t)bh * Wd + wg) * Dd;
#pragma unroll
            for (int nt = 0; nt < 6; nt++) {
                // acc[..][2rh]   -> G[w_l, s_l],   d0 = w_l + 63 - s_l
                // acc[..][2rh+1] -> G[w_l, s_l+1], d1 = d0 - 1
                const int d0 = 63 + 16 * mt + 8 * rh + q - 48 * h - 8 * nt - 2 * c;
                if (d0 >= 0 && d0 < 64) {
                    const float v0 = (d0 <= wg - 1) ? acc[mt][nt][2 * rh] * scale : 0.0f;
                    orow[d0] = v0;
                }
                if (d0 - 1 >= 0 && d0 - 1 < 64) {
                    const float v1 = (d0 - 1 <= wg - 1) ? acc[mt][nt][2 * rh + 1] * scale : 0.0f;
                    orow[d0 - 1] = v1;
                }
            }
        }
}

extern "C" void kernel_launch(void* const* d_in, const int* in_sizes, int n_in,
                              void* d_out, int out_size) {
    const float* left  = (const float*)d_in[0];
    const float* right = (const float*)d_in[1];
    float* outp = (float*)d_out;

    const int BH = in_sizes[0] / (Wd * Cd);

    cudaFuncSetAttribute(cost_volume_mma_kernel,
                         cudaFuncAttributeMaxDynamicSharedMemorySize, SMEM_BYTES);
    dim3 grid(Wd / WT, BH, 1);
    cost_volume_mma_kernel<<<grid, 256, SMEM_BYTES>>>(left, right, outp);
}

// round 15
// speedup vs baseline: 1.2482x; 1.2482x over previous
#include <cuda_runtime.h>

typedef unsigned int u32;

// CostVolume via banded tf32 GEMM (mma.sync m16n8k8), single-phase smem,
// LDS.128 k-window fragment loads, smem-staged coalesced epilogue.
// Block = (bh, 128-w tile), 256 threads / 8 warps.
// Warp wid: G[16,80] = L[rows 16wid..+15, 0..63] . R[rows 16wid..+79, 0..63]^T
// (R row r <-> src = w0-64+r), out[w,d] = G[w_l, w_l+63-d]/64, masked src<0.

namespace {
constexpr int Wd = 512, Cd = 64, Dd = 64, WT = 128;
constexpr int P        = 80;              // pitch (words): granule-bijective
constexpr int LS_WORDS = 128 * P;         // 10240
constexpr int SMEM_BYTES = (128 + 192) * P * 4;   // 102,400
constexpr int STG_P    = 68;              // staging pitch (words)
}

__device__ __forceinline__ u32 f2tf32(float x) {
    u32 r;
    asm("cvt.rna.tf32.f32 %0, %1;" : "=r"(r) : "f"(x));
    return r;
}
__device__ __forceinline__ void mma_tf32(float* d, const u32* a, u32 b0, u32 b1) {
    asm("mma.sync.aligned.m16n8k8.row.col.f32.tf32.tf32.f32 "
        "{%0,%1,%2,%3}, {%4,%5,%6,%7}, {%8,%9}, {%0,%1,%2,%3};"
        : "+f"(d[0]), "+f"(d[1]), "+f"(d[2]), "+f"(d[3])
        : "r"(a[0]), "r"(a[1]), "r"(a[2]), "r"(a[3]), "r"(b0), "r"(b1));
}

__global__ __launch_bounds__(256, 2)
void cost_volume_mma_kernel(const float* __restrict__ left,
                            const float* __restrict__ right,
                            float* __restrict__ out) {
    extern __shared__ u32 sm[];
    u32* Ls = sm;                 // [w_local 0..127][c 0..63], pitch P
    u32* Rs = sm + LS_WORDS;      // [s_local 0..191][c 0..63], pitch P

    const int tid  = threadIdx.x;
    const int wid  = tid >> 5;        // 0..7
    const int lane = tid & 31;
    const int q    = lane >> 2;       // 0..7
    const int c    = lane & 3;        // 0..3
    const int w0   = blockIdx.x * WT;
    const int bh   = blockIdx.y;

    const float* lrow = left  + (size_t)bh * Wd * Cd;
    const float* rrow = right + (size_t)bh * Wd * Cd;

    // ---- single fill: all 64 channels, tf32-converted at fill ----
#pragma unroll
    for (int i = 0; i < 8; i++) {
        const int idx = tid + 256 * i;          // 0..2047
        const int row = idx >> 4, c4 = idx & 15;
        const float4 v = *(const float4*)(lrow + (size_t)(w0 + row) * Cd + 4 * c4);
        uint4 t = make_uint4(f2tf32(v.x), f2tf32(v.y), f2tf32(v.z), f2tf32(v.w));
        *(uint4*)&Ls[row * P + 4 * c4] = t;
    }
#pragma unroll
    for (int i = 0; i < 12; i++) {
        const int idx = tid + 256 * i;          // 0..3071
        const int row = idx >> 4, c4 = idx & 15;
        const int s = max(w0 - 64 + row, 0);    // clamped; masked later
        const float4 v = *(const float4*)(rrow + (size_t)s * Cd + 4 * c4);
        uint4 t = make_uint4(f2tf32(v.x), f2tf32(v.y), f2tf32(v.z), f2tf32(v.w));
        *(uint4*)&Rs[row * P + 4 * c4] = t;
    }
    __syncthreads();

    // ---- compute: 4 supersteps of 16 k (k-window permuted, v4 loads) ----
    float acc[10][4];
#pragma unroll
    for (int nt = 0; nt < 10; nt++)
#pragma unroll
        for (int r = 0; r < 4; r++) acc[nt][r] = 0.0f;

    const u32* la_base = &Ls[(16 * wid + q) * P];
    const u32* rb_base = &Rs[(16 * wid + q) * P];
#pragma unroll
    for (int ki = 0; ki < 4; ki++) {
        const int kb = 16 * ki + 4 * c;
        const uint4 alo = *(const uint4*)(la_base + kb);
        const uint4 ahi = *(const uint4*)(la_base + 8 * P + kb);
        uint4 bv[10];
#pragma unroll
        for (int nt = 0; nt < 10; nt++)
            bv[nt] = *(const uint4*)(rb_base + (8 * nt) * P + kb);

        // sub-step 0: regs {x, z} -> phys k = {4c, 4c+2}
        {
            u32 a[4] = {alo.x, ahi.x, alo.z, ahi.z};
#pragma unroll
            for (int nt = 0; nt < 10; nt++)
                mma_tf32(acc[nt], a, bv[nt].x, bv[nt].z);
        }
        // sub-step 1: regs {y, w} -> phys k = {4c+1, 4c+3}
        {
            u32 a[4] = {alo.y, ahi.y, alo.w, ahi.w};
#pragma unroll
            for (int nt = 0; nt < 10; nt++)
                mma_tf32(acc[nt], a, bv[nt].y, bv[nt].w);
        }
    }

    // ---- epilogue: diagonal extraction into smem staging ----
    __syncthreads();
    float* stage = (float*)sm;                    // [128][STG_P]
    const float scale = 1.0f / 64.0f;
#pragma unroll
    for (int nt = 0; nt < 10; nt++)
#pragma unroll
        for (int r = 0; r < 4; r++) {
            const int d = 63 + q + 8 * (r >> 1) - 8 * nt - 2 * c - (r & 1);
            if (d >= 0 && d < 64) {
                const int w_l = 16 * wid + q + 8 * (r >> 1);
                const int s_l = w_l + 63 - d;
                const float val = (w0 + s_l >= 64) ? acc[nt][r] * scale : 0.0f;
                stage[w_l * STG_P + d] = val;
            }
        }
    __syncthreads();

    // ---- coalesced copy staging -> gmem ----
#pragma unroll
    for (int i = 0; i < 8; i++) {
        const int idx = tid + 256 * i;           // 0..2047
        const int row = idx >> 4, c4 = idx & 15;
        const float4 v = *(const float4*)(stage + row * STG_P + 4 * c4);
        *(float4*)(out + ((size_t)bh * Wd + w0 + row) * Dd + 4 * c4) = v;
    }
}

extern "C" void kernel_launch(void* const* d_in, const int* in_sizes, int n_in,
                              void* d_out, int out_size) {
    const float* left  = (const float*)d_in[0];
    const float* right = (const float*)d_in[1];
    float* outp = (float*)d_out;

    const int BH = in_sizes[0] / (Wd * Cd);

    cudaFuncSetAttribute(cost_volume_mma_kernel,
                         cudaFuncAttributeMaxDynamicSharedMemorySize, SMEM_BYTES);
    dim3 grid(Wd / WT, BH, 1);
    cost_volume_mma_kernel<<<grid, 256, SMEM_BYTES>>>(left, right, outp);
}

// round 16
// speedup vs baseline: 1.9516x; 1.5635x over previous
#include <cuda_runtime.h>
#include <cuda_fp16.h>

typedef unsigned int u32;

// CostVolume via banded fp16 GEMM (mma.sync m16n8k16, fp32 accumulate).
// Block = (bh, 128-w tile), 256 threads / 8 warps, single-phase smem (fp16).
// Warp wid: G[16,80] = L[rows 16wid..+15, 0..63] . R[rows 16wid..+79, 0..63]^T
// (R row r <-> src = w0-64+r), out[w,d] = G[w_l, w_l+63-d]/64, masked src<0.
// fp16 mantissa (10 bits) == tf32 mantissa; inputs ~N(0,1) so no range issue;
// accumulation in fp32 -> same error class as tf32 (~3e-4).

namespace {
constexpr int Wd = 512, Cd = 64, Dd = 64, WT = 128;
constexpr int PH       = 80;              // smem pitch in halves (granule-bijective)
constexpr int LS_HALVES = 128 * PH;       // 10240
constexpr int SMEM_BYTES = (128 + 192) * PH * 2;   // 51,200
constexpr int STG_P    = 68;              // staging pitch (f32 words)
}

__device__ __forceinline__ void mma_f16(float* d, const u32* a, u32 b0, u32 b1) {
    asm("mma.sync.aligned.m16n8k16.row.col.f32.f16.f16.f32 "
        "{%0,%1,%2,%3}, {%4,%5,%6,%7}, {%8,%9}, {%0,%1,%2,%3};"
        : "+f"(d[0]), "+f"(d[1]), "+f"(d[2]), "+f"(d[3])
        : "r"(a[0]), "r"(a[1]), "r"(a[2]), "r"(a[3]), "r"(b0), "r"(b1));
}
__device__ __forceinline__ u32 pack_h2(float lo, float hi) {
    const __half2 h = __floats2half2_rn(lo, hi);
    return *(const u32*)&h;
}

__global__ __launch_bounds__(256, 3)
void cost_volume_mma_kernel(const float* __restrict__ left,
                            const float* __restrict__ right,
                            float* __restrict__ out) {
    extern __shared__ __half smh[];
    __half* Ls = smh;                  // [w_local 0..127][c 0..63], pitch PH
    __half* Rs = smh + LS_HALVES;      // [s_local 0..191][c 0..63], pitch PH

    const int tid  = threadIdx.x;
    const int wid  = tid >> 5;        // 0..7
    const int lane = tid & 31;
    const int q    = lane >> 2;       // 0..7
    const int c    = lane & 3;        // 0..3
    const int w0   = blockIdx.x * WT;
    const int bh   = blockIdx.y;

    const float* lrow = left  + (size_t)bh * Wd * Cd;
    const float* rrow = right + (size_t)bh * Wd * Cd;

    // ---- single fill: all 64 channels, f32 -> fp16 at fill ----
#pragma unroll
    for (int i = 0; i < 8; i++) {
        const int idx = tid + 256 * i;          // 0..2047
        const int row = idx >> 4, c4 = idx & 15;
        const float4 v = *(const float4*)(lrow + (size_t)(w0 + row) * Cd + 4 * c4);
        const uint2 t = make_uint2(pack_h2(v.x, v.y), pack_h2(v.z, v.w));
        *(uint2*)&Ls[row * PH + 4 * c4] = t;
    }
#pragma unroll
    for (int i = 0; i < 12; i++) {
        const int idx = tid + 256 * i;          // 0..3071
        const int row = idx >> 4, c4 = idx & 15;
        const int s = max(w0 - 64 + row, 0);    // clamped; masked later
        const float4 v = *(const float4*)(rrow + (size_t)s * Cd + 4 * c4);
        const uint2 t = make_uint2(pack_h2(v.x, v.y), pack_h2(v.z, v.w));
        *(uint2*)&Rs[row * PH + 4 * c4] = t;
    }
    __syncthreads();

    // ---- compute: 4 K-steps of 16 (k-permuted phi(k), LDS.64 fragments) ----
    float acc[10][4];
#pragma unroll
    for (int nt = 0; nt < 10; nt++)
#pragma unroll
        for (int r = 0; r < 4; r++) acc[nt][r] = 0.0f;

    const __half* la_base = &Ls[(16 * wid + q) * PH];
    const __half* rb_base = &Rs[(16 * wid + q) * PH];
#pragma unroll
    for (int ki = 0; ki < 4; ki++) {
        const int kb = 16 * ki + 4 * c;         // phys halves base
        // A fragments: rows q and q+8; regs a0,a2 from row q, a1,a3 from q+8
        const uint2 alo = *(const uint2*)(la_base + kb);
        const uint2 ahi = *(const uint2*)(la_base + 8 * PH + kb);
        const u32 a[4] = {alo.x, ahi.x, alo.y, ahi.y};
#pragma unroll
        for (int nt = 0; nt < 10; nt++) {
            const uint2 bb = *(const uint2*)(rb_base + (8 * nt) * PH + kb);
            mma_f16(acc[nt], a, bb.x, bb.y);
        }
    }

    // ---- epilogue: diagonal extraction into smem staging ----
    __syncthreads();
    float* stage = (float*)smh;                   // [128][STG_P] f32
    const float scale = 1.0f / 64.0f;
#pragma unroll
    for (int nt = 0; nt < 10; nt++)
#pragma unroll
        for (int r = 0; r < 4; r++) {
            const int d = 63 + q + 8 * (r >> 1) - 8 * nt - 2 * c - (r & 1);
            if (d >= 0 && d < 64) {
                const int w_l = 16 * wid + q + 8 * (r >> 1);
                const int s_l = w_l + 63 - d;
                const float val = (w0 + s_l >= 64) ? acc[nt][r] * scale : 0.0f;
                stage[w_l * STG_P + d] = val;
            }
        }
    __syncthreads();

    // ---- coalesced copy staging -> gmem ----
#pragma unroll
    for (int i = 0; i < 8; i++) {
        const int idx = tid + 256 * i;           // 0..2047
        const int row = idx >> 4, c4 = idx & 15;
        const float4 v = *(const float4*)(stage + row * STG_P + 4 * c4);
        *(float4*)(out + ((size_t)bh * Wd + w0 + row) * Dd + 4 * c4) = v;
    }
}

extern "C" void kernel_launch(void* const* d_in, const int* in_sizes, int n_in,
                              void* d_out, int out_size) {
    const float* left  = (const float*)d_in[0];
    const float* right = (const float*)d_in[1];
    float* outp = (float*)d_out;

    const int BH = in_sizes[0] / (Wd * Cd);

    // staging (34.8KB f32) exceeds the fp16 tile region? no: 51.2KB >= 34.8KB ok
    cudaFuncSetAttribute(cost_volume_mma_kernel,
                         cudaFuncAttributeMaxDynamicSharedMemorySize, SMEM_BYTES);
    dim3 grid(Wd / WT, BH, 1);
    cost_volume_mma_kernel<<<grid, 256, SMEM_BYTES>>>(left, right, outp);
}